// round 1
// baseline (speedup 1.0000x reference)
#include <cuda_runtime.h>
#include <cstdint>

#define NEGV (-999999.0f)

constexpr int B = 2, H = 16, L = 2048, D = 64;
constexpr int BQ = 64, BK = 64;
constexpr int PAD = 65;            // smem row stride in floats (conflict-free scalar LDS)
constexpr int THREADS = 256;

// scratch: per-(b,h) mean over all 2048 value rows (for fully-masked query rows)
__device__ float g_vmean[B * H * D];

// ---------------------------------------------------------------------------
// Pre-kernel: column means of V per (b,h)
// ---------------------------------------------------------------------------
__global__ void vmean_kernel(const float* __restrict__ V) {
    int bh = blockIdx.x;                 // 0..31
    int d  = threadIdx.x & 63;           // 0..63
    int c  = threadIdx.x >> 6;           // 0..3 (chunk of 512 rows)
    __shared__ float part[4][64];
    const float* vp = V + (size_t)bh * L * D;
    float s = 0.f;
    int k0 = c * 512;
    for (int k = k0; k < k0 + 512; ++k) s += vp[(size_t)k * D + d];
    part[c][d] = s;
    __syncthreads();
    if (c == 0) {
        float t = part[0][d] + part[1][d] + part[2][d] + part[3][d];
        g_vmean[bh * D + d] = t * (1.0f / 2048.0f);
    }
}

// ---------------------------------------------------------------------------
// Flash-attention style kernel, fp32, 64x64 tiles, online softmax
// ---------------------------------------------------------------------------
__global__ __launch_bounds__(THREADS, 1)
void attn_kernel(const float* __restrict__ Q, const float* __restrict__ K,
                 const float* __restrict__ V, const int* __restrict__ qmask,
                 const int* __restrict__ vmask, const float* __restrict__ bias,
                 float* __restrict__ out) {
    extern __shared__ float smem[];
    float* Qs = smem;                    // [BQ][PAD]
    float* Ks = Qs + BQ * PAD;           // [BK][PAD]
    float* Vs = Ks + BK * PAD;           // [BK][PAD]
    float* Ps = Vs + BK * PAD;           // [BQ][PAD]
    int*   vms = (int*)(Ps + BQ * PAD);  // [BK]

    const int qt = blockIdx.x;           // q tile
    const int bh = blockIdx.y;           // b*H+h
    const int q0 = qt * BQ;

    const float* Qg = Q + ((size_t)bh * L + q0) * D;
    const float* Kg = K + (size_t)bh * L * D;
    const float* Vg = V + (size_t)bh * L * D;
    const float* Bg = bias + ((size_t)bh * L + q0) * L;

    const int tid = threadIdx.x;
    const int tx = tid & 15;             // col group (k-cols / d-dims)
    const int ty = tid >> 4;             // row group (q-rows)

    // load Q tile
    for (int idx = tid; idx < BQ * D; idx += THREADS)
        Qs[(idx >> 6) * PAD + (idx & 63)] = Qg[idx];

    float m[4], l[4], o[4][4];
#pragma unroll
    for (int i = 0; i < 4; ++i) {
        m[i] = -1e30f; l[i] = 0.f;
#pragma unroll
        for (int j = 0; j < 4; ++j) o[i][j] = 0.f;
    }

    const int nkt = qt + 1;              // causal: only tiles with k0 <= q_max
    for (int kt = 0; kt < nkt; ++kt) {
        const int k0 = kt * BK;
        __syncthreads();                 // protect Ks/Vs/Ps from previous iter readers
        for (int idx = tid; idx < BK * D; idx += THREADS) {
            Ks[(idx >> 6) * PAD + (idx & 63)] = Kg[(size_t)k0 * D + idx];
            Vs[(idx >> 6) * PAD + (idx & 63)] = Vg[(size_t)k0 * D + idx];
        }
        if (tid < BK) vms[tid] = vmask[(size_t)bh * L + k0 + tid];
        __syncthreads();

        // S = Q K^T  (4x4 register tile per thread)
        float s[4][4];
#pragma unroll
        for (int i = 0; i < 4; ++i)
#pragma unroll
            for (int j = 0; j < 4; ++j) s[i][j] = 0.f;

#pragma unroll 8
        for (int d = 0; d < D; ++d) {
            float qv[4], kv[4];
#pragma unroll
            for (int i = 0; i < 4; ++i) qv[i] = Qs[(ty + 16 * i) * PAD + d];
#pragma unroll
            for (int j = 0; j < 4; ++j) kv[j] = Ks[(tx + 16 * j) * PAD + d];
#pragma unroll
            for (int i = 0; i < 4; ++i)
#pragma unroll
                for (int j = 0; j < 4; ++j) s[i][j] += qv[i] * kv[j];
        }

        // scale + bias + mask
#pragma unroll
        for (int i = 0; i < 4; ++i) {
            int r = ty + 16 * i;
            int gq = q0 + r;
#pragma unroll
            for (int j = 0; j < 4; ++j) {
                int c = tx + 16 * j;
                int gk = k0 + c;
                float sc = s[i][j] * 0.125f + Bg[(size_t)r * L + gk];
                bool ok = (vms[c] != 0) && (gk <= gq);
                s[i][j] = ok ? sc : NEGV;
            }
        }

        // online softmax per row (reduce over 16 tx lanes)
#pragma unroll
        for (int i = 0; i < 4; ++i) {
            float tm = fmaxf(fmaxf(s[i][0], s[i][1]), fmaxf(s[i][2], s[i][3]));
#pragma unroll
            for (int off = 8; off >= 1; off >>= 1)
                tm = fmaxf(tm, __shfl_xor_sync(0xffffffffu, tm, off));
            float newm = fmaxf(m[i], tm);
            float alpha = __expf(m[i] - newm);
            float sum = 0.f;
#pragma unroll
            for (int j = 0; j < 4; ++j) {
                s[i][j] = __expf(s[i][j] - newm);
                sum += s[i][j];
            }
#pragma unroll
            for (int off = 8; off >= 1; off >>= 1)
                sum += __shfl_xor_sync(0xffffffffu, sum, off);
            l[i] = l[i] * alpha + sum;
            m[i] = newm;
#pragma unroll
            for (int j = 0; j < 4; ++j) o[i][j] *= alpha;
            // stage P
#pragma unroll
            for (int j = 0; j < 4; ++j)
                Ps[(ty + 16 * i) * PAD + tx + 16 * j] = s[i][j];
        }
        __syncthreads();

        // O += P V   (rows = q, cols = d)
#pragma unroll 8
        for (int k = 0; k < BK; ++k) {
            float vv[4], pv[4];
#pragma unroll
            for (int j = 0; j < 4; ++j) vv[j] = Vs[k * PAD + tx + 16 * j];
#pragma unroll
            for (int i = 0; i < 4; ++i) pv[i] = Ps[(ty + 16 * i) * PAD + k];
#pragma unroll
            for (int i = 0; i < 4; ++i)
#pragma unroll
                for (int j = 0; j < 4; ++j) o[i][j] += pv[i] * vv[j];
        }
    }

    // epilogue
#pragma unroll
    for (int i = 0; i < 4; ++i) {
        int r = ty + 16 * i;
        int gq = q0 + r;
        int qm = qmask[(size_t)bh * L + gq];
        float inv_l = 1.0f / l[i];
        bool fully_masked = (m[i] < -1e5f);   // all-NEG row -> uniform over ALL 2048 keys
#pragma unroll
        for (int j = 0; j < 4; ++j) {
            int d = tx + 16 * j;
            float res;
            if (!qm)               res = 0.f;
            else if (fully_masked) res = g_vmean[bh * D + d];
            else                   res = o[i][j] * inv_l;
            out[((size_t)bh * L + gq) * D + d] = res;
        }
    }
}

// ---------------------------------------------------------------------------
extern "C" void kernel_launch(void* const* d_in, const int* in_sizes, int n_in,
                              void* d_out, int out_size) {
    const float* Q  = (const float*)d_in[0];
    const float* K  = (const float*)d_in[1];
    const float* V  = (const float*)d_in[2];
    const int* qm   = (const int*)d_in[3];
    const int* vm   = (const int*)d_in[4];
    const float* bi = (const float*)d_in[5];
    float* out = (float*)d_out;

    constexpr int SMEM_BYTES = (4 * BQ * PAD) * (int)sizeof(float) + BK * (int)sizeof(int);
    cudaFuncSetAttribute(attn_kernel, cudaFuncAttributeMaxDynamicSharedMemorySize, SMEM_BYTES);

    vmean_kernel<<<B * H, 256>>>(V);
    attn_kernel<<<dim3(L / BQ, B * H), THREADS, SMEM_BYTES>>>(Q, K, V, qm, vm, bi, out);
}

// round 4
// speedup vs baseline: 2.0829x; 2.0829x over previous
#include <cuda_runtime.h>
#include <cstdint>

#define NEGV (-999999.0f)

constexpr int B = 2, H = 16, L = 2048, D = 64;
constexpr int BQ = 64, BK = 64;
constexpr int PADW = 68;               // smem row stride (floats): 4g+tig bank map, 16B-aligned rows
constexpr int THREADS = 128;           // 4 warps, each owns m16 of the 64-row q tile

// per-(b,h) mean over all 2048 value rows (fully-masked-row fallback: softmax(NEG vector) is uniform)
__device__ float g_vmean[B * H * D];

__global__ void vmean_kernel(const float* __restrict__ V) {
    int bh = blockIdx.x;
    int d  = threadIdx.x & 63;
    int c  = threadIdx.x >> 6;
    __shared__ float part[4][64];
    const float* vp = V + (size_t)bh * L * D;
    float s = 0.f;
    int k0 = c * 512;
    for (int k = k0; k < k0 + 512; ++k) s += vp[(size_t)k * D + d];
    part[c][d] = s;
    __syncthreads();
    if (c == 0)
        g_vmean[bh * D + d] = (part[0][d] + part[1][d] + part[2][d] + part[3][d]) * (1.0f / 2048.0f);
}

__device__ __forceinline__ uint32_t tf32r(float f) {
    uint32_t u; asm("cvt.rna.tf32.f32 %0, %1;" : "=r"(u) : "f"(f)); return u;
}
__device__ __forceinline__ float tf32f(float f) { return __uint_as_float(tf32r(f)); }
__device__ __forceinline__ uint32_t fau(float f) { return __float_as_uint(f); }

__device__ __forceinline__ void mma8(float* c, uint32_t a0, uint32_t a1, uint32_t a2, uint32_t a3,
                                     uint32_t b0, uint32_t b1) {
    asm volatile(
        "mma.sync.aligned.m16n8k8.row.col.f32.tf32.tf32.f32 "
        "{%0,%1,%2,%3},{%4,%5,%6,%7},{%8,%9},{%0,%1,%2,%3};"
        : "+f"(c[0]), "+f"(c[1]), "+f"(c[2]), "+f"(c[3])
        : "r"(a0), "r"(a1), "r"(a2), "r"(a3), "r"(b0), "r"(b1));
}

__global__ __launch_bounds__(THREADS, 1)
void attn_kernel(const float* __restrict__ Q, const float* __restrict__ K,
                 const float* __restrict__ V, const int* __restrict__ qmask,
                 const int* __restrict__ vmask, const float* __restrict__ bias,
                 float* __restrict__ out) {
    extern __shared__ float smem[];
    float* Qs = smem;                   // [64][PADW]  q-rows x d   (pre-scaled, tf32)
    float* Ks = Qs + BQ * PADW;         // [64][PADW]  keys   x d   (tf32)
    float* Vt = Ks + BK * PADW;         // [64][PADW]  d x keys     (tf32, transposed)
    float* Ps = Vt + BK * PADW;         // [64][PADW]  q-rows x keys (tf32 probs)
    int*   vms = (int*)(Ps + BQ * PADW);

    const int qt = blockIdx.x;
    const int bh = blockIdx.y;
    const int q0 = qt * BQ;

    const float* Qg = Q + ((size_t)bh * L + q0) * D;
    const float* Kg = K + (size_t)bh * L * D;
    const float* Vg = V + (size_t)bh * L * D;
    const float* Bg = bias + ((size_t)bh * L + q0) * L;

    const int tid = threadIdx.x;
    const int w = tid >> 5;             // warp: q rows [16w, 16w+16)
    const int lane = tid & 31;
    const int g = lane >> 2;            // groupID (row within fragment)
    const int tig = lane & 3;           // threadID_in_group

    // stage Q (scaled, tf32-rounded)
    for (int idx = tid * 4; idx < BQ * D; idx += THREADS * 4) {
        float4 v = *(const float4*)(Qg + idx);
        int r = idx >> 6, c = idx & 63;
        float* p = Qs + r * PADW + c;
        p[0] = tf32f(v.x * 0.125f); p[1] = tf32f(v.y * 0.125f);
        p[2] = tf32f(v.z * 0.125f); p[3] = tf32f(v.w * 0.125f);
    }

    float o[8][4];
    float m0 = -1e30f, m1 = -1e30f, l0 = 0.f, l1 = 0.f;
#pragma unroll
    for (int j = 0; j < 8; ++j) { o[j][0] = o[j][1] = o[j][2] = o[j][3] = 0.f; }

    const int row0 = 16 * w + g;        // local q row (and row0+8)
    const int gq0 = q0 + row0, gq1 = gq0 + 8;

    const int nkt = qt + 1;
    for (int kt = 0; kt < nkt; ++kt) {
        const int k0 = kt * BK;
        __syncthreads();
        // stage K and V^T (tf32)
        for (int idx = tid * 4; idx < BK * D; idx += THREADS * 4) {
            int r = idx >> 6, c = idx & 63;
            float4 kv = *(const float4*)(Kg + (size_t)(k0 + r) * D + c);
            float* kp = Ks + r * PADW + c;
            kp[0] = tf32f(kv.x); kp[1] = tf32f(kv.y); kp[2] = tf32f(kv.z); kp[3] = tf32f(kv.w);
            float4 vv = *(const float4*)(Vg + (size_t)(k0 + r) * D + c);
            Vt[(c + 0) * PADW + r] = tf32f(vv.x);
            Vt[(c + 1) * PADW + r] = tf32f(vv.y);
            Vt[(c + 2) * PADW + r] = tf32f(vv.z);
            Vt[(c + 3) * PADW + r] = tf32f(vv.w);
        }
        if (tid < BK) vms[tid] = vmask[(size_t)bh * L + k0 + tid];
        __syncthreads();

        // ---- S = Q K^T  (m16 x n64, k=64) ----
        float s[8][4];
#pragma unroll
        for (int j = 0; j < 8; ++j) { s[j][0] = s[j][1] = s[j][2] = s[j][3] = 0.f; }
#pragma unroll
        for (int kk = 0; kk < 8; ++kk) {
            int ca = 8 * kk + tig;
            uint32_t a0 = fau(Qs[row0 * PADW + ca]);
            uint32_t a1 = fau(Qs[(row0 + 8) * PADW + ca]);
            uint32_t a2 = fau(Qs[row0 * PADW + ca + 4]);
            uint32_t a3 = fau(Qs[(row0 + 8) * PADW + ca + 4]);
#pragma unroll
            for (int j = 0; j < 8; ++j) {
                uint32_t b0 = fau(Ks[(8 * j + g) * PADW + ca]);
                uint32_t b1 = fau(Ks[(8 * j + g) * PADW + ca + 4]);
                mma8(s[j], a0, a1, a2, a3, b0, b1);
            }
        }

        // ---- bias + mask (scale already folded into Q) ----
#pragma unroll
        for (int j = 0; j < 8; ++j) {
            int c0 = k0 + 8 * j + 2 * tig;
            float2 bv0 = *(const float2*)(Bg + (size_t)row0 * L + c0);
            float2 bv1 = *(const float2*)(Bg + (size_t)(row0 + 8) * L + c0);
            bool mk0 = vms[8 * j + 2 * tig] != 0;
            bool mk1 = vms[8 * j + 2 * tig + 1] != 0;
            s[j][0] = (mk0 && c0     <= gq0) ? s[j][0] + bv0.x : NEGV;
            s[j][1] = (mk1 && c0 + 1 <= gq0) ? s[j][1] + bv0.y : NEGV;
            s[j][2] = (mk0 && c0     <= gq1) ? s[j][2] + bv1.x : NEGV;
            s[j][3] = (mk1 && c0 + 1 <= gq1) ? s[j][3] + bv1.y : NEGV;
        }

        // ---- online softmax (rows row0 and row0+8; reduce over tig quad) ----
        float tm0 = -1e30f, tm1 = -1e30f;
#pragma unroll
        for (int j = 0; j < 8; ++j) {
            tm0 = fmaxf(tm0, fmaxf(s[j][0], s[j][1]));
            tm1 = fmaxf(tm1, fmaxf(s[j][2], s[j][3]));
        }
        tm0 = fmaxf(tm0, __shfl_xor_sync(0xffffffffu, tm0, 1));
        tm0 = fmaxf(tm0, __shfl_xor_sync(0xffffffffu, tm0, 2));
        tm1 = fmaxf(tm1, __shfl_xor_sync(0xffffffffu, tm1, 1));
        tm1 = fmaxf(tm1, __shfl_xor_sync(0xffffffffu, tm1, 2));
        float nm0 = fmaxf(m0, tm0), nm1 = fmaxf(m1, tm1);
        float al0 = __expf(m0 - nm0), al1 = __expf(m1 - nm1);
        m0 = nm0; m1 = nm1;
        float sum0 = 0.f, sum1 = 0.f;
#pragma unroll
        for (int j = 0; j < 8; ++j) {
            s[j][0] = __expf(s[j][0] - m0); sum0 += s[j][0];
            s[j][1] = __expf(s[j][1] - m0); sum0 += s[j][1];
            s[j][2] = __expf(s[j][2] - m1); sum1 += s[j][2];
            s[j][3] = __expf(s[j][3] - m1); sum1 += s[j][3];
        }
        sum0 += __shfl_xor_sync(0xffffffffu, sum0, 1);
        sum0 += __shfl_xor_sync(0xffffffffu, sum0, 2);
        sum1 += __shfl_xor_sync(0xffffffffu, sum1, 1);
        sum1 += __shfl_xor_sync(0xffffffffu, sum1, 2);
        l0 = l0 * al0 + sum0;
        l1 = l1 * al1 + sum1;
#pragma unroll
        for (int j = 0; j < 8; ++j) {
            o[j][0] *= al0; o[j][1] *= al0; o[j][2] *= al1; o[j][3] *= al1;
            // stage P (tf32) — warp-private rows, no CTA sync needed
            int c = 8 * j + 2 * tig;
            *(float2*)(Ps + row0 * PADW + c) =
                make_float2(tf32f(s[j][0]), tf32f(s[j][1]));
            *(float2*)(Ps + (row0 + 8) * PADW + c) =
                make_float2(tf32f(s[j][2]), tf32f(s[j][3]));
        }
        __syncwarp();

        // ---- O += P V  (m16 x n64, k=64 keys) ----
#pragma unroll
        for (int kk = 0; kk < 8; ++kk) {
            int ca = 8 * kk + tig;
            uint32_t a0 = fau(Ps[row0 * PADW + ca]);
            uint32_t a1 = fau(Ps[(row0 + 8) * PADW + ca]);
            uint32_t a2 = fau(Ps[row0 * PADW + ca + 4]);
            uint32_t a3 = fau(Ps[(row0 + 8) * PADW + ca + 4]);
#pragma unroll
            for (int j = 0; j < 8; ++j) {
                uint32_t b0 = fau(Vt[(8 * j + g) * PADW + ca]);
                uint32_t b1 = fau(Vt[(8 * j + g) * PADW + ca + 4]);
                mma8(o[j], a0, a1, a2, a3, b0, b1);
            }
        }
        __syncwarp();   // protect Ps before next iteration's rewrite
    }

    // ---- epilogue ----
    int qm0 = qmask[(size_t)bh * L + gq0];
    int qm1 = qmask[(size_t)bh * L + gq1];
    bool fm0 = (m0 < -1e5f), fm1 = (m1 < -1e5f);
    float il0 = 1.0f / l0, il1 = 1.0f / l1;
#pragma unroll
    for (int j = 0; j < 8; ++j) {
        int c = 8 * j + 2 * tig;
        float2 r0, r1;
        r0.x = !qm0 ? 0.f : (fm0 ? g_vmean[bh * D + c]     : o[j][0] * il0);
        r0.y = !qm0 ? 0.f : (fm0 ? g_vmean[bh * D + c + 1] : o[j][1] * il0);
        r1.x = !qm1 ? 0.f : (fm1 ? g_vmean[bh * D + c]     : o[j][2] * il1);
        r1.y = !qm1 ? 0.f : (fm1 ? g_vmean[bh * D + c + 1] : o[j][3] * il1);
        *(float2*)(out + ((size_t)bh * L + gq0) * D + c) = r0;
        *(float2*)(out + ((size_t)bh * L + gq1) * D + c) = r1;
    }
}

// ---------------------------------------------------------------------------
extern "C" void kernel_launch(void* const* d_in, const int* in_sizes, int n_in,
                              void* d_out, int out_size) {
    const float* Q  = (const float*)d_in[0];
    const float* K  = (const float*)d_in[1];
    const float* V  = (const float*)d_in[2];
    const int* qm   = (const int*)d_in[3];
    const int* vm   = (const int*)d_in[4];
    const float* bi = (const float*)d_in[5];
    float* out = (float*)d_out;

    constexpr int SMEM_BYTES = 4 * BQ * PADW * (int)sizeof(float) + BK * (int)sizeof(int);
    cudaFuncSetAttribute(attn_kernel, cudaFuncAttributeMaxDynamicSharedMemorySize, SMEM_BYTES);

    vmean_kernel<<<B * H, 256>>>(V);
    attn_kernel<<<dim3(L / BQ, B * H), THREADS, SMEM_BYTES>>>(Q, K, V, qm, vm, bi, out);
}

// round 6
// speedup vs baseline: 2.5365x; 1.2178x over previous
#include <cuda_runtime.h>
#include <cstdint>

#define NEGV (-999999.0f)

constexpr int B = 2, H = 16, L = 2048, D = 64;
constexpr int BQ = 64, BK = 64;
constexpr int PW = 72;                // smem row stride (floats), conflict-free LDS.64
constexpr int THREADS = 128;

// scratch (pre-converted tf32, mma-friendly layouts)
__device__ float g_Kc[B * H * L * D];   // [bh][key][d']   d interleaved within 8-groups
__device__ float g_Vt[B * H * D * L];   // [bh][d][key']   transposed, key interleaved
__device__ float g_vmean[B * H * D];

__device__ __forceinline__ int perm8(int k) { return 2 * (k & 3) + ((k >> 2) & 1); }
__device__ __forceinline__ int iperm8(int c) { return ((c & 1) << 2) + (c >> 1); }

__device__ __forceinline__ uint32_t tf32r(float f) {
    uint32_t u; asm("cvt.rna.tf32.f32 %0, %1;" : "=r"(u) : "f"(f)); return u;
}
__device__ __forceinline__ float tf32f(float f) { return __uint_as_float(tf32r(f)); }
__device__ __forceinline__ uint32_t fau(float f) { return __float_as_uint(f); }

__device__ __forceinline__ void mma8(float* c, uint32_t a0, uint32_t a1, uint32_t a2, uint32_t a3,
                                     uint32_t b0, uint32_t b1) {
    asm volatile(
        "mma.sync.aligned.m16n8k8.row.col.f32.tf32.tf32.f32 "
        "{%0,%1,%2,%3},{%4,%5,%6,%7},{%8,%9},{%0,%1,%2,%3};"
        : "+f"(c[0]), "+f"(c[1]), "+f"(c[2]), "+f"(c[3])
        : "r"(a0), "r"(a1), "r"(a2), "r"(a3), "r"(b0), "r"(b1));
}

__device__ __forceinline__ void cp_async16(uint32_t saddr, const void* g) {
    asm volatile("cp.async.cg.shared.global [%0], [%1], 16;" :: "r"(saddr), "l"(g));
}

// ---------------------------------------------------------------------------
// Pre-pass kernels
// ---------------------------------------------------------------------------
__global__ void kprep_kernel(const float* __restrict__ K) {
    int idx = blockIdx.x * 256 + threadIdx.x;          // over B*H*L*D
    float v = K[idx];
    int d = idx & 63;
    int dst = (idx & ~63) | (d & ~7) | perm8(d & 7);
    g_Kc[dst] = tf32f(v);
}

__global__ void vtrans_kernel(const float* __restrict__ V) {
    // grid (L/64, B*H); 64key x 64d tile transpose with key-interleave
    __shared__ float t[64][65];
    int k0 = blockIdx.x * 64;
    int bh = blockIdx.y;
    const float* vp = V + ((size_t)bh * L + k0) * D;
    int tid = threadIdx.x;
#pragma unroll
    for (int i = 0; i < 16; ++i) {
        int e = i * 256 + tid;
        t[e >> 6][e & 63] = vp[e];
    }
    __syncthreads();
    float* op = g_Vt + (size_t)bh * D * L + k0;
#pragma unroll
    for (int i = 0; i < 16; ++i) {
        int e = i * 256 + tid;
        int d = e >> 6, c = e & 63;                    // c = key' within tile
        int key = (c & ~7) | iperm8(c & 7);
        op[(size_t)d * L + c] = tf32f(t[key][d]);
    }
}

__global__ void vmean_kernel(const float* __restrict__ V) {
    int bh = blockIdx.x;
    int d  = threadIdx.x & 63;
    int c  = threadIdx.x >> 6;
    __shared__ float part[4][64];
    const float* vp = V + (size_t)bh * L * D;
    float s = 0.f;
    for (int k = c * 512; k < c * 512 + 512; ++k) s += vp[(size_t)k * D + d];
    part[c][d] = s;
    __syncthreads();
    if (c == 0)
        g_vmean[bh * D + d] = (part[0][d] + part[1][d] + part[2][d] + part[3][d]) * (1.0f / 2048.0f);
}

// ---------------------------------------------------------------------------
// Main attention kernel
// ---------------------------------------------------------------------------
__global__ __launch_bounds__(THREADS)
void attn_kernel(const float* __restrict__ Q, const int* __restrict__ qmask,
                 const int* __restrict__ vmask, const float* __restrict__ bias,
                 float* __restrict__ out) {
    extern __shared__ float smem[];
    float* Qs = smem;                        // [64][PW]  interleaved d
    float* Ps = Qs + BQ * PW;                // [64][PW]  interleaved key
    float* Ks[2] = { Ps + BQ * PW, Ps + BQ * PW + BK * PW };        // [key][d'] raw copy of g_Kc
    float* Vs[2] = { Ks[1] + BK * PW, Ks[1] + 2 * BK * PW };        // [d][key'] raw copy of g_Vt

    const int qt = blockIdx.x;
    const int bh = blockIdx.y;
    const int q0 = qt * BQ;

    const float* Qg = Q + ((size_t)bh * L + q0) * D;
    const float* Kg = g_Kc + (size_t)bh * L * D;
    const float* Vg = g_Vt + (size_t)bh * D * L;
    const float* Bg = bias + ((size_t)bh * L + q0) * L;
    const int*  vmg = vmask + (size_t)bh * L;

    const int tid = threadIdx.x;
    const int w = tid >> 5, lane = tid & 31;
    const int g = lane >> 2, tig = lane & 3;

    const uint32_t sKs[2] = { (uint32_t)__cvta_generic_to_shared(Ks[0]),
                              (uint32_t)__cvta_generic_to_shared(Ks[1]) };
    const uint32_t sVs[2] = { (uint32_t)__cvta_generic_to_shared(Vs[0]),
                              (uint32_t)__cvta_generic_to_shared(Vs[1]) };

    const int nkt = qt + 1;

    // prefetch tile 0 (buf 0): full 64x64 tile = 1024 chunks -> 8 chunks/thread/array
    {
#pragma unroll
        for (int i = 0; i < 8; ++i) {
            int c = tid + i * 128;
            int r = c >> 4, sg = (c & 15) * 4;
            cp_async16(sKs[0] + (r * PW + sg) * 4, Kg + r * 64 + sg);
            cp_async16(sVs[0] + (r * PW + sg) * 4, Vg + (size_t)r * L + sg);
        }
        asm volatile("cp.async.commit_group;");
    }

    // stage Q (scaled, tf32, d-interleaved)
    for (int idx = tid * 4; idx < BQ * D; idx += THREADS * 4) {
        float4 v = *(const float4*)(Qg + idx);
        int r = idx >> 6, c = idx & 63;
        float* p = Qs + r * PW + (c & ~7);
        int half = (c >> 2) & 1;                     // 0: within-group 0..3, 1: 4..7
        p[half + 0] = tf32f(v.x * 0.125f);
        p[half + 2] = tf32f(v.y * 0.125f);
        p[half + 4] = tf32f(v.z * 0.125f);
        p[half + 6] = tf32f(v.w * 0.125f);
    }

    float o[8][4];
    float m0 = -1e30f, m1 = -1e30f, l0 = 0.f, l1 = 0.f;
#pragma unroll
    for (int j = 0; j < 8; ++j) { o[j][0] = o[j][1] = o[j][2] = o[j][3] = 0.f; }

    const int row0 = 16 * w + g;
    const int gq0 = q0 + row0, gq1 = gq0 + 8;
    const int pofs0 = ((tig & 1) << 2) + (tig >> 1);   // Ps store offsets (interleaved)
    const int pofs1 = pofs0 + 2;

    for (int kt = 0; kt < nkt; ++kt) {
        const int k0 = kt * BK;
        const int buf = kt & 1;
        asm volatile("cp.async.wait_group 0;");
        __syncthreads();

        // prefetch next tile into the other buffer (safe: __syncthreads above
        // means every warp finished the previous iteration's reads of it)
        if (kt + 1 < nkt) {
            const int nk0 = (kt + 1) * BK;
            const int nb = buf ^ 1;
#pragma unroll
            for (int i = 0; i < 8; ++i) {
                int c = tid + i * 128;
                int r = c >> 4, sg = (c & 15) * 4;
                cp_async16(sKs[nb] + (r * PW + sg) * 4, Kg + (size_t)(nk0 + r) * 64 + sg);
                cp_async16(sVs[nb] + (r * PW + sg) * 4, Vg + (size_t)r * L + nk0 + sg);
            }
            asm volatile("cp.async.commit_group;");
        }

        // bias + mask prefetch (in flight during S-mma)
        float2 bv0[8], bv1[8]; int2 vmk[8];
#pragma unroll
        for (int j = 0; j < 8; ++j) {
            int c0 = k0 + 8 * j + 2 * tig;
            bv0[j] = *(const float2*)(Bg + (size_t)row0 * L + c0);
            bv1[j] = *(const float2*)(Bg + (size_t)(row0 + 8) * L + c0);
            vmk[j] = *(const int2*)(vmg + c0);
        }

        // ---- S = Q K^T ----
        float s[8][4];
#pragma unroll
        for (int j = 0; j < 8; ++j) { s[j][0] = s[j][1] = s[j][2] = s[j][3] = 0.f; }
        const float* Kb = Ks[buf];
#pragma unroll
        for (int kk = 0; kk < 8; ++kk) {
            int co = 8 * kk + 2 * tig;
            float2 aA = *(const float2*)(Qs + row0 * PW + co);        // (a0, a2)
            float2 aB = *(const float2*)(Qs + (row0 + 8) * PW + co);  // (a1, a3)
#pragma unroll
            for (int j = 0; j < 8; ++j) {
                float2 b = *(const float2*)(Kb + (8 * j + g) * PW + co);
                mma8(s[j], fau(aA.x), fau(aB.x), fau(aA.y), fau(aB.y), fau(b.x), fau(b.y));
            }
        }

        // ---- bias + mask ----
#pragma unroll
        for (int j = 0; j < 8; ++j) {
            int c0 = k0 + 8 * j + 2 * tig;
            bool mk0 = vmk[j].x != 0, mk1 = vmk[j].y != 0;
            s[j][0] = (mk0 && c0     <= gq0) ? s[j][0] + bv0[j].x : NEGV;
            s[j][1] = (mk1 && c0 + 1 <= gq0) ? s[j][1] + bv0[j].y : NEGV;
            s[j][2] = (mk0 && c0     <= gq1) ? s[j][2] + bv1[j].x : NEGV;
            s[j][3] = (mk1 && c0 + 1 <= gq1) ? s[j][3] + bv1[j].y : NEGV;
        }

        // ---- online softmax ----
        float tm0 = -1e30f, tm1 = -1e30f;
#pragma unroll
        for (int j = 0; j < 8; ++j) {
            tm0 = fmaxf(tm0, fmaxf(s[j][0], s[j][1]));
            tm1 = fmaxf(tm1, fmaxf(s[j][2], s[j][3]));
        }
        tm0 = fmaxf(tm0, __shfl_xor_sync(0xffffffffu, tm0, 1));
        tm0 = fmaxf(tm0, __shfl_xor_sync(0xffffffffu, tm0, 2));
        tm1 = fmaxf(tm1, __shfl_xor_sync(0xffffffffu, tm1, 1));
        tm1 = fmaxf(tm1, __shfl_xor_sync(0xffffffffu, tm1, 2));
        float nm0 = fmaxf(m0, tm0), nm1 = fmaxf(m1, tm1);
        float al0 = __expf(m0 - nm0), al1 = __expf(m1 - nm1);
        m0 = nm0; m1 = nm1;
        float sum0 = 0.f, sum1 = 0.f;
#pragma unroll
        for (int j = 0; j < 8; ++j) {
            s[j][0] = __expf(s[j][0] - m0); sum0 += s[j][0];
            s[j][1] = __expf(s[j][1] - m0); sum0 += s[j][1];
            s[j][2] = __expf(s[j][2] - m1); sum1 += s[j][2];
            s[j][3] = __expf(s[j][3] - m1); sum1 += s[j][3];
        }
        sum0 += __shfl_xor_sync(0xffffffffu, sum0, 1);
        sum0 += __shfl_xor_sync(0xffffffffu, sum0, 2);
        sum1 += __shfl_xor_sync(0xffffffffu, sum1, 1);
        sum1 += __shfl_xor_sync(0xffffffffu, sum1, 2);
        l0 = l0 * al0 + sum0;
        l1 = l1 * al1 + sum1;
#pragma unroll
        for (int j = 0; j < 8; ++j) {
            o[j][0] *= al0; o[j][1] *= al0; o[j][2] *= al1; o[j][3] *= al1;
            float* pr0 = Ps + row0 * PW + 8 * j;
            float* pr1 = Ps + (row0 + 8) * PW + 8 * j;
            pr0[pofs0] = tf32f(s[j][0]);
            pr0[pofs1] = tf32f(s[j][1]);
            pr1[pofs0] = tf32f(s[j][2]);
            pr1[pofs1] = tf32f(s[j][3]);
        }
        __syncwarp();

        // ---- O += P V ----
        const float* Vb = Vs[buf];
#pragma unroll
        for (int kk = 0; kk < 8; ++kk) {
            int co = 8 * kk + 2 * tig;
            float2 aA = *(const float2*)(Ps + row0 * PW + co);
            float2 aB = *(const float2*)(Ps + (row0 + 8) * PW + co);
#pragma unroll
            for (int j = 0; j < 8; ++j) {
                float2 b = *(const float2*)(Vb + (8 * j + g) * PW + co);
                mma8(o[j], fau(aA.x), fau(aB.x), fau(aA.y), fau(aB.y), fau(b.x), fau(b.y));
            }
        }
        __syncwarp();   // protect Ps before next iteration's rewrite
    }

    // ---- epilogue ----
    int qm0 = qmask[(size_t)bh * L + gq0];
    int qm1 = qmask[(size_t)bh * L + gq1];
    bool fm0 = (m0 < -1e5f), fm1 = (m1 < -1e5f);
    float il0 = 1.0f / l0, il1 = 1.0f / l1;
#pragma unroll
    for (int j = 0; j < 8; ++j) {
        int c = 8 * j + 2 * tig;
        float2 r0, r1;
        r0.x = !qm0 ? 0.f : (fm0 ? g_vmean[bh * D + c]     : o[j][0] * il0);
        r0.y = !qm0 ? 0.f : (fm0 ? g_vmean[bh * D + c + 1] : o[j][1] * il0);
        r1.x = !qm1 ? 0.f : (fm1 ? g_vmean[bh * D + c]     : o[j][2] * il1);
        r1.y = !qm1 ? 0.f : (fm1 ? g_vmean[bh * D + c + 1] : o[j][3] * il1);
        *(float2*)(out + ((size_t)bh * L + gq0) * D + c) = r0;
        *(float2*)(out + ((size_t)bh * L + gq1) * D + c) = r1;
    }
}

// ---------------------------------------------------------------------------
extern "C" void kernel_launch(void* const* d_in, const int* in_sizes, int n_in,
                              void* d_out, int out_size) {
    const float* Q  = (const float*)d_in[0];
    const float* K  = (const float*)d_in[1];
    const float* V  = (const float*)d_in[2];
    const int* qm   = (const int*)d_in[3];
    const int* vm   = (const int*)d_in[4];
    const float* bi = (const float*)d_in[5];
    float* out = (float*)d_out;

    constexpr int SMEM_BYTES = 6 * BQ * PW * (int)sizeof(float);
    cudaFuncSetAttribute(attn_kernel, cudaFuncAttributeMaxDynamicSharedMemorySize, SMEM_BYTES);

    kprep_kernel<<<(B * H * L * D) / 256, 256>>>(K);
    vtrans_kernel<<<dim3(L / 64, B * H), 256>>>(V);
    vmean_kernel<<<B * H, 256>>>(V);
    attn_kernel<<<dim3(L / BQ, B * H), THREADS, SMEM_BYTES>>>(Q, qm, vm, bi, out);
}